// round 12
// baseline (speedup 1.0000x reference)
#include <cuda_runtime.h>
#include <stdint.h>

#define D        2048
#define KSEL     512
#define THREADS  256
#define MAX_ROWS 32768

// 2048 bits per row = 64 words; 32768 rows -> 8 MB scratch
__device__ uint32_t g_mask[(long long)MAX_ROWS * 64];

// ============================================================================
// Kernel 1: exact per-row top-k threshold + mask bitfield (1 block per row)
// ============================================================================
__global__ __launch_bounds__(THREADS, 8)
void select_kernel(const float* __restrict__ randv)
{
    __shared__ uint32_t s_hist[256];
    __shared__ uint32_t s_wsum[8];
    __shared__ uint32_t s_sel[2];     // [0]=digit, [1]=remaining-after
    __shared__ uint32_t s_lotot;
    __shared__ uint32_t s_m[64];      // packed row mask

    const int t    = threadIdx.x;
    const int lane = t & 31;
    const int wid  = t >> 5;
    const long long base = (long long)blockIdx.x * D;

    // ---- rand row -> 8 registers (two coalesced float4s) ----
    uint32_t b[8];
    {
        const float4* r4 = (const float4*)(randv + base);
        float4 r0 = r4[t];          // elements 4t .. 4t+3
        float4 r1 = r4[t + 256];    // elements 1024+4t .. 1024+4t+3
        b[0] = __float_as_uint(r0.x); b[1] = __float_as_uint(r0.y);
        b[2] = __float_as_uint(r0.z); b[3] = __float_as_uint(r0.w);
        b[4] = __float_as_uint(r1.x); b[5] = __float_as_uint(r1.y);
        b[6] = __float_as_uint(r1.z); b[7] = __float_as_uint(r1.w);
    }
    if (t < 64) s_m[t] = 0;

    // ---- radix select: 4 passes of 8 bits, MSB first ----
    uint32_t prefHi    = 0;
    uint32_t remaining = KSEL;

    #pragma unroll
    for (int shift = 24; shift >= 0; shift -= 8) {
        s_hist[t] = 0;
        __syncthreads();

        #pragma unroll
        for (int j = 0; j < 8; j++) {
            bool active = (shift == 24) ||
                          ((b[j] >> (shift + 8)) == (prefHi >> (shift + 8)));
            uint32_t digit = (b[j] >> shift) & 0xFFu;
            uint32_t key = active ? digit : 0x100u;
            unsigned peers = __match_any_sync(0xFFFFFFFFu, key);
            if (active && lane == (__ffs(peers) - 1))
                atomicAdd(&s_hist[digit], (uint32_t)__popc(peers));
        }
        __syncthreads();

        // one warp picks: largest digit d with count(>d) < remaining <= count(>=d)
        if (t < 32) {
            uint32_t local[8];
            uint32_t lsum = 0;
            #pragma unroll
            for (int j = 0; j < 8; j++) { local[j] = s_hist[t * 8 + j]; lsum += local[j]; }
            uint32_t x = lsum;   // inclusive suffix-sum over lanes >= t
            #pragma unroll
            for (int off = 1; off < 32; off <<= 1) {
                uint32_t y = __shfl_down_sync(0xFFFFFFFFu, x, off);
                if (t + off < 32) x += y;
            }
            uint32_t c = x - lsum;    // count with digit >= (t+1)*8
            int found = -1; uint32_t remAfter = 0;
            for (int j = 7; j >= 0; j--) {
                uint32_t nc = c + local[j];
                if (found < 0 && c < remaining && remaining <= nc) {
                    found = t * 8 + j;
                    remAfter = remaining - c;
                }
                c = nc;
            }
            if (found >= 0) { s_sel[0] = (uint32_t)found; s_sel[1] = remAfter; }
        }
        __syncthreads();
        prefHi   |= s_sel[0] << shift;
        remaining = s_sel[1];
        __syncthreads();   // protect s_sel/s_hist before next pass
    }

    const uint32_t T       = prefHi;
    const uint32_t need_eq = remaining;

    // ---- mask bits + exact tie-break in global index order ----
    // thread t owns: lo indices 4t+j (j=0..3), hi indices 1024+4t+(j-4) (j=4..7)
    uint32_t mk = 0, eqm = 0;
    uint32_t cnt_lo = 0, cnt_hi = 0;
    #pragma unroll
    for (int j = 0; j < 8; j++) {
        bool gt = b[j] > T;
        bool eq = b[j] == T;
        if (gt) mk  |= 1u << j;
        if (eq) eqm |= 1u << j;
        if (eq) { if (j < 4) cnt_lo++; else cnt_hi++; }
    }

    {
        uint32_t v  = cnt_lo | (cnt_hi << 16);
        uint32_t sc = v;
        #pragma unroll
        for (int off = 1; off < 32; off <<= 1) {
            uint32_t y = __shfl_up_sync(0xFFFFFFFFu, sc, off);
            if (lane >= off) sc += y;
        }
        if (lane == 31) s_wsum[wid] = sc;
        __syncthreads();
        uint32_t wbase = 0;
        #pragma unroll
        for (int w = 0; w < 8; w++) if (w < wid) wbase += s_wsum[w];
        if (t == THREADS - 1) s_lotot = (wbase + sc) & 0xFFFFu;  // total lo equals
        uint32_t ex = wbase + sc - v;                            // exclusive prefix
        __syncthreads();
        uint32_t r_lo = ex & 0xFFFFu;
        uint32_t r_hi = s_lotot + (ex >> 16);

        #pragma unroll
        for (int j = 0; j < 4; j++) {
            if (eqm & (1u << j)) { if (r_lo < need_eq) mk |= 1u << j; r_lo++; }
        }
        #pragma unroll
        for (int j = 4; j < 8; j++) {
            if (eqm & (1u << j)) { if (r_hi < need_eq) mk |= 1u << j; r_hi++; }
        }
    }

    // ---- pack into 64-word row bitfield ----
    // lo bits j=0..3 -> elem 4t+j   -> word t>>3,      bit 4*(t&7)+j
    // hi bits j=4..7 -> elem 1024+4t+(j-4) -> word 32+(t>>3), bit 4*(t&7)+(j-4)
    {
        int sh = 4 * (t & 7);
        atomicOr(&s_m[t >> 3],        (mk & 0xFu)        << sh);
        atomicOr(&s_m[32 + (t >> 3)], ((mk >> 4) & 0xFu) << sh);
        __syncthreads();
        if (t < 64) g_mask[(long long)blockIdx.x * 64 + t] = s_m[t];
    }
}

// ============================================================================
// Kernel 2: pure streaming apply — 8 consecutive elements per thread
// ============================================================================
__global__ __launch_bounds__(THREADS)
void apply_kernel(const float* __restrict__ data,
                  const float* __restrict__ noise,
                  float* __restrict__ out_masked,
                  float* __restrict__ out_inv)
{
    const long long tid = (long long)blockIdx.x * THREADS + threadIdx.x;
    const uint8_t* mb = (const uint8_t*)g_mask;
    uint32_t m8 = mb[tid];               // mask byte: bits 0..7 -> elems 8*tid .. 8*tid+7

    const float4* d4 = (const float4*)data;
    const float4* n4 = (const float4*)noise;
    float4* oA = (float4*)out_masked;
    float4* oB = (float4*)out_inv;

    long long v = tid * 2;
    float4 dd0 = d4[v],     dd1 = d4[v + 1];
    float4 nn0 = n4[v],     nn1 = n4[v + 1];

    float4 m0, m1, i0, i1;
    bool k0 = m8 & 1u,   k1 = m8 & 2u,   k2 = m8 & 4u,   k3 = m8 & 8u;
    bool k4 = m8 & 16u,  k5 = m8 & 32u,  k6 = m8 & 64u,  k7 = m8 & 128u;

    m0.x = k0 ? 0.0f : fmaf(0.1f, nn0.x, dd0.x);
    m0.y = k1 ? 0.0f : fmaf(0.1f, nn0.y, dd0.y);
    m0.z = k2 ? 0.0f : fmaf(0.1f, nn0.z, dd0.z);
    m0.w = k3 ? 0.0f : fmaf(0.1f, nn0.w, dd0.w);
    m1.x = k4 ? 0.0f : fmaf(0.1f, nn1.x, dd1.x);
    m1.y = k5 ? 0.0f : fmaf(0.1f, nn1.y, dd1.y);
    m1.z = k6 ? 0.0f : fmaf(0.1f, nn1.z, dd1.z);
    m1.w = k7 ? 0.0f : fmaf(0.1f, nn1.w, dd1.w);

    i0.x = k0 ? 0.0f : 1.0f;  i0.y = k1 ? 0.0f : 1.0f;
    i0.z = k2 ? 0.0f : 1.0f;  i0.w = k3 ? 0.0f : 1.0f;
    i1.x = k4 ? 0.0f : 1.0f;  i1.y = k5 ? 0.0f : 1.0f;
    i1.z = k6 ? 0.0f : 1.0f;  i1.w = k7 ? 0.0f : 1.0f;

    oA[v]     = m0;
    oA[v + 1] = m1;
    oB[v]     = i0;
    oB[v + 1] = i1;
}

extern "C" void kernel_launch(void* const* d_in, const int* in_sizes, int n_in,
                              void* d_out, int out_size)
{
    const float* data  = (const float*)d_in[0];
    const float* noise = (const float*)d_in[1];
    const float* randv = (const float*)d_in[2];
    float* out = (float*)d_out;

    long long N = (long long)in_sizes[0];     // 67108864
    int rows = (int)(N / D);                  // 32768

    select_kernel<<<rows, THREADS>>>(randv);

    int apply_blocks = (int)(N / (8LL * THREADS));   // 8 elems per thread
    apply_kernel<<<apply_blocks, THREADS>>>(data, noise, out, out + N);
}